// round 1
// baseline (speedup 1.0000x reference)
#include <cuda_runtime.h>

#define NV 32      // nodes per graph
#define NE 256     // edges per graph
#define NH 4       // heads
#define DH 64      // dim per head
#define CC 256     // NH*DH
#define K1 128     // layer-1 input dim
#define K2 64      // layer-2 input dim
#define ST 33      // padded stride for [C][node] buffers
#define ST2 36     // padded stride for [k][node] buffers (16B-aligned rows)
#define NT 256     // threads per block
#define NGRAPHS 2048

struct __align__(16) Smem {
    float xs[NV * K1];        // 4096 f : x tile (layer1); reused as h2 [DH][ST2] (2304 f)
    float bufA[CC * ST];      // 8448 f : hs (src projection), layout [c][node]
    float bufB[CC * ST];      // 8448 f : hd (dst projection); reused as aggregation out
    float h1[DH * ST2];       // 2304 f : layer-1 output, layout [k][node]
    float logits[NE * NH];
    float alpha[NE * NH];
    float aw[CC];             // attention vector for current layer
    float mx[NV * NH];
    float den[NV * NH];
    float nalpha[NV];
    int esrc[NE];
    int edst[NE];
    int cnt[NV];
    int startv[NV + 1];
};

// out[32, 256] = xs[32, 128] @ W[128, 256] + b ; one thread per output column.
__device__ __forceinline__ void gemm_k128(const float* __restrict__ W,
                                          const float* __restrict__ b,
                                          const float* __restrict__ xs,
                                          float* __restrict__ outbuf, int c)
{
    float acc[NV];
    const float bias = __ldg(&b[c]);
#pragma unroll
    for (int r = 0; r < NV; r++) acc[r] = bias;
    for (int k = 0; k < K1; k += 4) {
        const float w0 = __ldg(&W[(k + 0) * CC + c]);
        const float w1 = __ldg(&W[(k + 1) * CC + c]);
        const float w2 = __ldg(&W[(k + 2) * CC + c]);
        const float w3 = __ldg(&W[(k + 3) * CC + c]);
#pragma unroll
        for (int r = 0; r < NV; r++) {
            const float4 xv = *reinterpret_cast<const float4*>(&xs[r * K1 + k]);
            acc[r] = fmaf(xv.x, w0, fmaf(xv.y, w1, fmaf(xv.z, w2, fmaf(xv.w, w3, acc[r]))));
        }
    }
#pragma unroll
    for (int r = 0; r < NV; r++) outbuf[c * ST + r] = acc[r];
}

// out[32, 256] = hin[32, 64] @ W[64, 256] + b ; hin stored [k][node] stride ST2.
__device__ __forceinline__ void gemm_k64(const float* __restrict__ W,
                                         const float* __restrict__ b,
                                         const float* __restrict__ hin,
                                         float* __restrict__ outbuf, int c)
{
    float acc[NV];
    const float bias = __ldg(&b[c]);
#pragma unroll
    for (int r = 0; r < NV; r++) acc[r] = bias;
#pragma unroll 4
    for (int k = 0; k < K2; k++) {
        const float w = __ldg(&W[k * CC + c]);
#pragma unroll
        for (int r = 0; r < NV; r += 4) {
            const float4 hv = *reinterpret_cast<const float4*>(&hin[k * ST2 + r]);
            acc[r + 0] = fmaf(hv.x, w, acc[r + 0]);
            acc[r + 1] = fmaf(hv.y, w, acc[r + 1]);
            acc[r + 2] = fmaf(hv.z, w, acc[r + 2]);
            acc[r + 3] = fmaf(hv.w, w, acc[r + 3]);
        }
    }
#pragma unroll
    for (int r = 0; r < NV; r++) outbuf[c * ST + r] = acc[r];
}

// GATv2 edge phase: logits -> edge softmax (per dst,head) -> weighted agg -> head maxpool.
// Reads bufA (hs) + bufB (hd); aggregation result overwrites bufB; maxpool into dest[k*ST2+v].
__device__ __forceinline__ void gat_edge_phase(Smem& s, const float* __restrict__ attn,
                                               float* __restrict__ dest, int tid)
{
    s.aw[tid] = __ldg(&attn[tid]);
    __syncthreads();

    // --- per-edge logits: a_h . leaky_relu(hs[src] + hd[dst]) ---
    {
        const int jj = tid;
        const int ss = s.esrc[jj], dd = s.edst[jj];
#pragma unroll
        for (int h = 0; h < NH; h++) {
            float lg = 0.f;
#pragma unroll 8
            for (int k = 0; k < DH; k++) {
                const int c = h * DH + k;
                const float v1 = s.bufA[c * ST + ss] + s.bufB[c * ST + dd];
                const float lr = v1 > 0.f ? v1 : 0.2f * v1;
                lg = fmaf(s.aw[c], lr, lg);
            }
            s.logits[jj * NH + h] = lg;
        }
    }
    __syncthreads();

    // --- per (node, head) max and exp-sum over incoming (sorted) edge segment ---
    if (tid < NV * NH) {
        const int v = tid >> 2, h = tid & 3;
        const int e0 = s.startv[v], e1 = s.startv[v + 1];
        float m = -1e30f;
        for (int j = e0; j < e1; j++) m = fmaxf(m, s.logits[j * NH + h]);
        float d = 0.f;
        for (int j = e0; j < e1; j++) d += expf(s.logits[j * NH + h] - m);
        s.mx[tid] = m;
        s.den[tid] = (d == 0.f) ? 1.f : d;
    }
    __syncthreads();

    // --- per-edge alpha ---
    {
        const int jj = tid, dd = s.edst[jj];
#pragma unroll
        for (int h = 0; h < NH; h++)
            s.alpha[jj * NH + h] =
                expf(s.logits[jj * NH + h] - s.mx[dd * NH + h]) / s.den[dd * NH + h];
    }
    __syncthreads();

    // --- aggregation: out[v][h][k] = sum_{e: dst=v} alpha * hs[src]  (writes bufB) ---
    {
        const int pr = tid >> 1, half = tid & 1;
        const int v = pr >> 2, h = pr & 3;
        const int kb = half * 32;
        float acc[32];
#pragma unroll
        for (int k = 0; k < 32; k++) acc[k] = 0.f;
        const int e0 = s.startv[v], e1 = s.startv[v + 1];
        for (int j = e0; j < e1; j++) {
            const float a = s.alpha[j * NH + h];
            const int ss = s.esrc[j];
#pragma unroll
            for (int k = 0; k < 32; k++)
                acc[k] = fmaf(a, s.bufA[(h * DH + kb + k) * ST + ss], acc[k]);
        }
#pragma unroll
        for (int k = 0; k < 32; k++)
            s.bufB[(h * DH + kb + k) * ST + v] = acc[k];
    }
    __syncthreads();

    // --- head maxpool -> dest[k][v] ---
    for (int i = tid; i < NV * DH; i += NT) {
        const int v = i & 31, k = i >> 5;
        float m = s.bufB[k * ST + v];
#pragma unroll
        for (int h = 1; h < NH; h++) m = fmaxf(m, s.bufB[(h * DH + k) * ST + v]);
        dest[k * ST2 + v] = m;
    }
    __syncthreads();
}

__global__ __launch_bounds__(NT, 2)
void gat_fused_kernel(const float* __restrict__ x,
                      const int* __restrict__ src,
                      const int* __restrict__ dst,
                      const float* __restrict__ W1s, const float* __restrict__ b1s,
                      const float* __restrict__ W1d, const float* __restrict__ b1d,
                      const float* __restrict__ a1,
                      const float* __restrict__ W2s, const float* __restrict__ b2s,
                      const float* __restrict__ W2d, const float* __restrict__ b2d,
                      const float* __restrict__ a2,
                      const float* __restrict__ Wg, const float* __restrict__ bg,
                      float* __restrict__ out)
{
    extern __shared__ unsigned char smraw[];
    Smem& s = *reinterpret_cast<Smem*>(smraw);
    const int g = blockIdx.x, tid = threadIdx.x;

    // ---- phase 0: load x tile, count-sort edges by dst ----
    {
        const float4* xg = reinterpret_cast<const float4*>(x + (size_t)g * NV * K1);
        float4* xsv = reinterpret_cast<float4*>(s.xs);
        for (int i = tid; i < NV * K1 / 4; i += NT) xsv[i] = __ldg(&xg[i]);

        const int rs = src[g * NE + tid] - g * NV;
        const int rd = dst[g * NE + tid] - g * NV;
        if (tid < NV) s.cnt[tid] = 0;
        __syncthreads();
        const int p = atomicAdd(&s.cnt[rd], 1);
        __syncthreads();
        if (tid == 0) {
            int acc = 0;
            for (int v = 0; v < NV; v++) { s.startv[v] = acc; acc += s.cnt[v]; }
            s.startv[NV] = acc;
        }
        __syncthreads();
        const int j = s.startv[rd] + p;
        s.esrc[j] = rs;
        s.edst[j] = rd;
    }
    __syncthreads();

    // ---- layer 1 ----
    gemm_k128(W1s, b1s, s.xs, s.bufA, tid);
    gemm_k128(W1d, b1d, s.xs, s.bufB, tid);
    __syncthreads();
    gat_edge_phase(s, a1, s.h1, tid);

    // ---- layer 2 (x tile no longer needed; h2 aliases it) ----
    gemm_k64(W2s, b2s, s.h1, s.bufA, tid);
    gemm_k64(W2d, b2d, s.h1, s.bufB, tid);
    __syncthreads();
    float* h2 = s.xs;
    gat_edge_phase(s, a2, h2, tid);

    // ---- global attention pooling ----
    if (tid < NV) {
        float gacc = __ldg(&bg[0]);
#pragma unroll
        for (int k = 0; k < DH; k++) gacc = fmaf(h2[k * ST2 + tid], __ldg(&Wg[k]), gacc);
        float m = gacc;
#pragma unroll
        for (int o = 16; o; o >>= 1) m = fmaxf(m, __shfl_xor_sync(0xffffffffu, m, o));
        const float ex = expf(gacc - m);
        float d = ex;
#pragma unroll
        for (int o = 16; o; o >>= 1) d += __shfl_xor_sync(0xffffffffu, d, o);
        s.nalpha[tid] = ex / d;
    }
    __syncthreads();
    if (tid < DH) {
        float r = 0.f;
#pragma unroll
        for (int v = 0; v < NV; v++) r = fmaf(s.nalpha[v], h2[tid * ST2 + v], r);
        out[(size_t)g * DH + tid] = r;
    }
}

extern "C" void kernel_launch(void* const* d_in, const int* in_sizes, int n_in,
                              void* d_out, int out_size)
{
    const float* x   = (const float*)d_in[0];
    const int*   src = (const int*)d_in[1];
    const int*   dst = (const int*)d_in[2];
    // d_in[3] = graph_ids (implicit in our blocking; unused)
    const float* W1s = (const float*)d_in[4];
    const float* b1s = (const float*)d_in[5];
    const float* W1d = (const float*)d_in[6];
    const float* b1d = (const float*)d_in[7];
    const float* a1  = (const float*)d_in[8];
    const float* W2s = (const float*)d_in[9];
    const float* b2s = (const float*)d_in[10];
    const float* W2d = (const float*)d_in[11];
    const float* b2d = (const float*)d_in[12];
    const float* a2  = (const float*)d_in[13];
    const float* Wg  = (const float*)d_in[14];
    const float* bg  = (const float*)d_in[15];
    float* out = (float*)d_out;

    const int smem = (int)sizeof(Smem);
    cudaFuncSetAttribute(gat_fused_kernel,
                         cudaFuncAttributeMaxDynamicSharedMemorySize, smem);
    gat_fused_kernel<<<NGRAPHS, NT, smem>>>(x, src, dst,
                                            W1s, b1s, W1d, b1d, a1,
                                            W2s, b2s, W2d, b2d, a2,
                                            Wg, bg, out);
}

// round 3
// speedup vs baseline: 1.2531x; 1.2531x over previous
#include <cuda_runtime.h>

#define NV 32      // nodes per graph
#define NE 256     // edges per graph
#define NH 4       // heads
#define DH 64      // dim per head
#define CC 256     // NH*DH
#define K1 128     // layer-1 input dim
#define K2 64      // layer-2 input dim
#define NT 256     // threads per block
#define NGRAPHS 2048

#define SR  260    // node-major stride (floats); 260/4=65 ≡ 1 (mod 32) -> conflict-free rows
#define SR4 65
#define STK 36     // k-major stride (floats), 16B aligned rows
#define STK4 9
#define HNS 68     // hN stride (floats)
#define HNS4 17

struct __align__(16) Smem {
    float xsT[K1 * STK];    // 4608 f : x transposed [k][node] (layer-1 A)
    float bufA[NV * SR];    // 8320 f : hs, node-major [node][c]
    float bufB[NV * SR];    // 8320 f : hd, node-major; reused as aggregation out
    float hT[DH * STK];     // 2304 f : maxpooled h, k-major [k][node] (next-GEMM A / readout)
    float hN[NV * HNS];     // 2176 f : maxpooled h, node-major [node][k] (pooling gate)
    float logits[NE * NH];  // 1024 f : logits, then alpha in place
    float aw[CC];
    float mx[NV * NH];
    float den[NV * NH];
    float nalpha[NV];
    int esrc[NE];
    int edst[NE];
    int cnt[NV];
    int startv[NV + 1];
};

__device__ __forceinline__ void fma4(float4& acc, float s, const float4 w) {
    acc.x = fmaf(s, w.x, acc.x);
    acc.y = fmaf(s, w.y, acc.y);
    acc.z = fmaf(s, w.z, acc.z);
    acc.w = fmaf(s, w.w, acc.w);
}

// C[32, 256] = A[32, K] @ W[K, 256] + b.
// A in smem, k-major float4 (stride STK4). Output node-major float4 (stride SR4).
// Thread layout: tr = tid>>6 (8-row group), tc = tid&63 (4-col group).
template <int K>
__device__ __forceinline__ void gemm(const float* __restrict__ W,
                                     const float* __restrict__ b,
                                     const float4* __restrict__ A4,
                                     float4* __restrict__ out4, int tid)
{
    const int tr = tid >> 6;       // 0..3 -> rows tr*8 .. tr*8+7
    const int tc = tid & 63;       // 0..63 -> cols tc*4 .. tc*4+3
    const float4* __restrict__ W4 = reinterpret_cast<const float4*>(W);
    const float4 bias = __ldg(&reinterpret_cast<const float4*>(b)[tc]);
    float4 acc[8];
#pragma unroll
    for (int i = 0; i < 8; i++) acc[i] = bias;

#pragma unroll 4
    for (int k = 0; k < K; k++) {
        const float4 a0 = A4[k * STK4 + tr * 2];
        const float4 a1 = A4[k * STK4 + tr * 2 + 1];
        const float4 w  = __ldg(&W4[k * 64 + tc]);
        fma4(acc[0], a0.x, w);
        fma4(acc[1], a0.y, w);
        fma4(acc[2], a0.z, w);
        fma4(acc[3], a0.w, w);
        fma4(acc[4], a1.x, w);
        fma4(acc[5], a1.y, w);
        fma4(acc[6], a1.z, w);
        fma4(acc[7], a1.w, w);
    }
#pragma unroll
    for (int i = 0; i < 8; i++) out4[(tr * 8 + i) * SR4 + tc] = acc[i];
}

// GATv2 edge phase: logits -> edge softmax -> weighted agg -> head maxpool.
// bufA = hs, bufB = hd (node-major). Aggregation overwrites bufB.
// Maxpool writes hT (k-major) and hN (node-major).
__device__ __forceinline__ void gat_edge_phase(Smem& s, const float* __restrict__ attn, int tid)
{
    s.aw[tid] = __ldg(&attn[tid]);
    __syncthreads();

    float4* bufA4 = reinterpret_cast<float4*>(s.bufA);
    float4* bufB4 = reinterpret_cast<float4*>(s.bufB);
    const float4* aw4 = reinterpret_cast<const float4*>(s.aw);

    // --- per-edge logits ---
    {
        const int j = tid;
        const int ss = s.esrc[j], dd = s.edst[j];
        const float4* pa = bufA4 + ss * SR4;
        const float4* pb = bufB4 + dd * SR4;
#pragma unroll
        for (int h = 0; h < NH; h++) {
            float lg = 0.f;
#pragma unroll
            for (int q = 0; q < 16; q++) {
                const float4 sa = pa[h * 16 + q];
                const float4 sb = pb[h * 16 + q];
                const float4 w  = aw4[h * 16 + q];
                float v;
                v = sa.x + sb.x; lg = fmaf(w.x, v > 0.f ? v : 0.2f * v, lg);
                v = sa.y + sb.y; lg = fmaf(w.y, v > 0.f ? v : 0.2f * v, lg);
                v = sa.z + sb.z; lg = fmaf(w.z, v > 0.f ? v : 0.2f * v, lg);
                v = sa.w + sb.w; lg = fmaf(w.w, v > 0.f ? v : 0.2f * v, lg);
            }
            s.logits[j * NH + h] = lg;
        }
    }
    __syncthreads();

    // --- per (node, head) max & exp-sum over sorted incoming-edge segment ---
    if (tid < NV * NH) {
        const int v = tid >> 2, h = tid & 3;
        const int e0 = s.startv[v], e1 = s.startv[v + 1];
        float m = -1e30f;
        for (int j = e0; j < e1; j++) m = fmaxf(m, s.logits[j * NH + h]);
        float d = 0.f;
        for (int j = e0; j < e1; j++) d += expf(s.logits[j * NH + h] - m);
        s.mx[tid]  = m;
        s.den[tid] = (d == 0.f) ? 1.f : d;
    }
    __syncthreads();

    // --- per-edge alpha, in place over logits ---
    {
        const int j = tid, dd = s.edst[j];
#pragma unroll
        for (int h = 0; h < NH; h++)
            s.logits[j * NH + h] =
                expf(s.logits[j * NH + h] - s.mx[dd * NH + h]) / s.den[dd * NH + h];
    }
    __syncthreads();

    // --- aggregation: bufB[v][c] = sum_{e: dst=v} alpha_e * hs[src_e][c] ---
    {
        const int v = tid >> 3;
        const int h = (tid >> 1) & 3;
        const int half = tid & 1;
        const int b0 = h * 16 + half * 8;   // float4 col base
        float4 acc[8];
#pragma unroll
        for (int q = 0; q < 8; q++) acc[q] = make_float4(0.f, 0.f, 0.f, 0.f);
        const int e0 = s.startv[v], e1 = s.startv[v + 1];
        for (int j = e0; j < e1; j++) {
            const float a = s.logits[j * NH + h];
            const float4* p = bufA4 + s.esrc[j] * SR4 + b0;
#pragma unroll
            for (int q = 0; q < 8; q++) fma4(acc[q], a, p[q]);
        }
#pragma unroll
        for (int q = 0; q < 8; q++) bufB4[v * SR4 + b0 + q] = acc[q];
    }
    __syncthreads();

    // --- head maxpool -> hT[k][v] and hN[v][k] ---
    float4* hN4 = reinterpret_cast<float4*>(s.hN);
    for (int i = tid; i < NV * DH / 4; i += NT) {
        const int v = i >> 4, q = i & 15;    // q = float4 index within 64 dims
        float4 m = bufB4[v * SR4 + q];
#pragma unroll
        for (int h = 1; h < NH; h++) {
            const float4 t = bufB4[v * SR4 + h * 16 + q];
            m.x = fmaxf(m.x, t.x); m.y = fmaxf(m.y, t.y);
            m.z = fmaxf(m.z, t.z); m.w = fmaxf(m.w, t.w);
        }
        hN4[v * HNS4 + q] = m;
        const int k0 = q * 4;
        s.hT[(k0 + 0) * STK + v] = m.x;
        s.hT[(k0 + 1) * STK + v] = m.y;
        s.hT[(k0 + 2) * STK + v] = m.z;
        s.hT[(k0 + 3) * STK + v] = m.w;
    }
    __syncthreads();
}

__global__ __launch_bounds__(NT, 2)
void gat_fused_kernel(const float* __restrict__ x,
                      const int* __restrict__ src,
                      const int* __restrict__ dst,
                      const float* __restrict__ W1s, const float* __restrict__ b1s,
                      const float* __restrict__ W1d, const float* __restrict__ b1d,
                      const float* __restrict__ a1,
                      const float* __restrict__ W2s, const float* __restrict__ b2s,
                      const float* __restrict__ W2d, const float* __restrict__ b2d,
                      const float* __restrict__ a2,
                      const float* __restrict__ Wg, const float* __restrict__ bg,
                      float* __restrict__ out)
{
    extern __shared__ unsigned char smraw[];
    Smem& s = *reinterpret_cast<Smem*>(smraw);
    const int g = blockIdx.x, tid = threadIdx.x;

    // ---- phase 0: load x transposed, count-sort edges by dst ----
    {
        const float* xg = x + (size_t)g * NV * K1;
        for (int i = tid; i < NV * K1; i += NT) {
            const int row = i >> 7, k = i & 127;
            s.xsT[k * STK + row] = __ldg(&xg[i]);
        }
        const int rs = src[g * NE + tid] - g * NV;
        const int rd = dst[g * NE + tid] - g * NV;
        if (tid < NV) s.cnt[tid] = 0;
        __syncthreads();
        const int p = atomicAdd(&s.cnt[rd], 1);
        __syncthreads();
        if (tid == 0) {
            int acc = 0;
            for (int v = 0; v < NV; v++) { s.startv[v] = acc; acc += s.cnt[v]; }
            s.startv[NV] = acc;
        }
        __syncthreads();
        const int j = s.startv[rd] + p;
        s.esrc[j] = rs;
        s.edst[j] = rd;
    }
    __syncthreads();

    float4* xsT4  = reinterpret_cast<float4*>(s.xsT);
    float4* hT4   = reinterpret_cast<float4*>(s.hT);
    float4* bufA4 = reinterpret_cast<float4*>(s.bufA);
    float4* bufB4 = reinterpret_cast<float4*>(s.bufB);

    // ---- layer 1 ----
    gemm<K1>(W1s, b1s, xsT4, bufA4, tid);
    gemm<K1>(W1d, b1d, xsT4, bufB4, tid);
    __syncthreads();
    gat_edge_phase(s, a1, tid);

    // ---- layer 2 ----
    gemm<K2>(W2s, b2s, hT4, bufA4, tid);
    gemm<K2>(W2d, b2d, hT4, bufB4, tid);
    __syncthreads();
    gat_edge_phase(s, a2, tid);   // overwrites hT/hN with h2

    // ---- global attention pooling ----
    if (tid < NV) {
        const float4* hN4 = reinterpret_cast<const float4*>(s.hN);
        const float4* wg4 = reinterpret_cast<const float4*>(Wg);
        float gacc = __ldg(&bg[0]);
#pragma unroll
        for (int q = 0; q < 16; q++) {
            const float4 hv = hN4[tid * HNS4 + q];
            const float4 w  = __ldg(&wg4[q]);
            gacc = fmaf(hv.x, w.x, gacc);
            gacc = fmaf(hv.y, w.y, gacc);
            gacc = fmaf(hv.z, w.z, gacc);
            gacc = fmaf(hv.w, w.w, gacc);
        }
        float m = gacc;
#pragma unroll
        for (int o = 16; o; o >>= 1) m = fmaxf(m, __shfl_xor_sync(0xffffffffu, m, o));
        const float ex = expf(gacc - m);
        float d = ex;
#pragma unroll
        for (int o = 16; o; o >>= 1) d += __shfl_xor_sync(0xffffffffu, d, o);
        s.nalpha[tid] = ex / d;
    }
    __syncthreads();
    if (tid < DH) {
        float r = 0.f;
#pragma unroll
        for (int v = 0; v < NV; v++) r = fmaf(s.nalpha[v], s.hT[tid * STK + v], r);
        out[(size_t)g * DH + tid] = r;
    }
}

extern "C" void kernel_launch(void* const* d_in, const int* in_sizes, int n_in,
                              void* d_out, int out_size)
{
    const float* x   = (const float*)d_in[0];
    const int*   src = (const int*)d_in[1];
    const int*   dst = (const int*)d_in[2];
    // d_in[3] = graph_ids (implicit in blocking; unused)
    const float* W1s = (const float*)d_in[4];
    const float* b1s = (const float*)d_in[5];
    const float* W1d = (const float*)d_in[6];
    const float* b1d = (const float*)d_in[7];
    const float* a1  = (const float*)d_in[8];
    const float* W2s = (const float*)d_in[9];
    const float* b2s = (const float*)d_in[10];
    const float* W2d = (const float*)d_in[11];
    const float* b2d = (const float*)d_in[12];
    const float* a2  = (const float*)d_in[13];
    const float* Wg  = (const float*)d_in[14];
    const float* bg  = (const float*)d_in[15];
    float* out = (float*)d_out;

    const int smem = (int)sizeof(Smem);
    cudaFuncSetAttribute(gat_fused_kernel,
                         cudaFuncAttributeMaxDynamicSharedMemorySize, smem);
    gat_fused_kernel<<<NGRAPHS, NT, smem>>>(x, src, dst,
                                            W1s, b1s, W1d, b1d, a1,
                                            W2s, b2s, W2d, b2d, a2,
                                            Wg, bg, out);
}

// round 5
// speedup vs baseline: 1.7071x; 1.3623x over previous
#include <cuda_runtime.h>

#define NV 32      // nodes per graph
#define NE 256     // edges per graph
#define NH 4       // heads
#define DH 64      // dim per head
#define CC 256     // NH*DH
#define K1 128     // layer-1 input dim
#define K2 64      // layer-2 input dim
#define NT 256     // threads per block
#define NGRAPHS 2048

#define SR4 65     // node-major row stride in float4 (65 ≡ 1 mod 32)
#define STK 36     // k-major stride (floats)
#define STK4 9
#define HNS4 17    // hN stride in float4
#define AMS 33     // Amat row stride in float4 (33 -> conflict-free across v)

struct __align__(16) Smem {
    float xsT[K1 * STK];    // 4608 f : x transposed [k][node]; reused as Amat (32*33*4=4224 f)
    float bufA[NV * SR4 * 4];   // hs, node-major [node][c]
    float bufB[NV * SR4 * 4];   // hd, node-major; overwritten by aggregation
    float hT[DH * STK];     // maxpooled h, k-major (next-GEMM A / readout)
    float hN[NV * HNS4 * 4];// maxpooled h, node-major (pooling gate)
    float logits[NE * NH];  // [e][h]
    float aw[CC];
    float mx[NV * NH];      // [v][h]
    float den[NV * NH];
    float nalpha[NV];
    int esrc[NE];
    int edst[NE];
    int cnt[NV];
    int startv[NV + 1];
};

__device__ __forceinline__ void fma4(float4& acc, float s, const float4 w) {
    acc.x = fmaf(s, w.x, acc.x);
    acc.y = fmaf(s, w.y, acc.y);
    acc.z = fmaf(s, w.z, acc.z);
    acc.w = fmaf(s, w.w, acc.w);
}

// C[32, 256] = A[32, K] @ W[K, 256] + b. A k-major float4 in smem; out node-major.
template <int K>
__device__ __forceinline__ void gemm(const float* __restrict__ W,
                                     const float* __restrict__ b,
                                     const float4* __restrict__ A4,
                                     float4* __restrict__ out4, int tid)
{
    const int tr = tid >> 6;
    const int tc = tid & 63;
    const float4* __restrict__ W4 = reinterpret_cast<const float4*>(W);
    const float4 bias = __ldg(&reinterpret_cast<const float4*>(b)[tc]);
    float4 acc[8];
#pragma unroll
    for (int i = 0; i < 8; i++) acc[i] = bias;
#pragma unroll 4
    for (int k = 0; k < K; k++) {
        const float4 a0 = A4[k * STK4 + tr * 2];
        const float4 a1 = A4[k * STK4 + tr * 2 + 1];
        const float4 w  = __ldg(&W4[k * 64 + tc]);
        fma4(acc[0], a0.x, w); fma4(acc[1], a0.y, w);
        fma4(acc[2], a0.z, w); fma4(acc[3], a0.w, w);
        fma4(acc[4], a1.x, w); fma4(acc[5], a1.y, w);
        fma4(acc[6], a1.z, w); fma4(acc[7], a1.w, w);
    }
#pragma unroll
    for (int i = 0; i < 8; i++) out4[(tr * 8 + i) * SR4 + tc] = acc[i];
}

// GATv2 edge phase. bufA = hs, bufB = hd (node-major). Agg overwrites bufB.
__device__ __forceinline__ void gat_edge_phase(Smem& s, const float* __restrict__ attn, int tid)
{
    s.aw[tid] = __ldg(&attn[tid]);
    __syncthreads();

    float4* bufA4 = reinterpret_cast<float4*>(s.bufA);
    float4* bufB4 = reinterpret_cast<float4*>(s.bufB);
    const float4* aw4 = reinterpret_cast<const float4*>(s.aw);
    float* Amat = s.xsT;                      // aliased: 32 x AMS float4
    float4* Amat4 = reinterpret_cast<float4*>(Amat);

    const int wid = tid >> 5, lane = tid & 31;
    const int eg = lane >> 3;                 // edge slot within warp (0..3)
    const int ln = lane & 7;                  // channel lane (0..7)

    // attention weights for this lane's channel chunks, cached in regs
    float4 awr[8];
#pragma unroll
    for (int c = 0; c < 8; c++) awr[c] = aw4[c * 8 + ln];

    // --- logits: 4 edges per warp pass, 8 lanes per edge (conflict-free 128B rows) ---
#pragma unroll 2
    for (int pass = 0; pass < 8; pass++) {
        const int e = wid * 32 + pass * 4 + eg;
        const int ss = s.esrc[e], dd = s.edst[e];
        const float4* pa = bufA4 + ss * SR4;
        const float4* pb = bufB4 + dd * SR4;
        float part[NH] = {0.f, 0.f, 0.f, 0.f};
#pragma unroll
        for (int c = 0; c < 8; c++) {
            const float4 sa = pa[c * 8 + ln];
            const float4 sb = pb[c * 8 + ln];
            const float4 w  = awr[c];
            const int h = c >> 1;
            float v;
            v = sa.x + sb.x; part[h] = fmaf(w.x, v > 0.f ? v : 0.2f * v, part[h]);
            v = sa.y + sb.y; part[h] = fmaf(w.y, v > 0.f ? v : 0.2f * v, part[h]);
            v = sa.z + sb.z; part[h] = fmaf(w.z, v > 0.f ? v : 0.2f * v, part[h]);
            v = sa.w + sb.w; part[h] = fmaf(w.w, v > 0.f ? v : 0.2f * v, part[h]);
        }
#pragma unroll
        for (int o = 4; o; o >>= 1) {
            part[0] += __shfl_xor_sync(0xffffffffu, part[0], o);
            part[1] += __shfl_xor_sync(0xffffffffu, part[1], o);
            part[2] += __shfl_xor_sync(0xffffffffu, part[2], o);
            part[3] += __shfl_xor_sync(0xffffffffu, part[3], o);
        }
        if (ln == 0)
            *reinterpret_cast<float4*>(&s.logits[e * NH]) =
                make_float4(part[0], part[1], part[2], part[3]);
    }
    __syncthreads();

    // --- per (node, head) max & exp-sum; other half zeroes Amat ---
    if (tid < NV * NH) {
        const int v = tid >> 2, h = tid & 3;
        const int e0 = s.startv[v], e1 = s.startv[v + 1];
        float m = -1e30f;
        for (int j = e0; j < e1; j++) m = fmaxf(m, s.logits[j * NH + h]);
        float d = 0.f;
        for (int j = e0; j < e1; j++) d += __expf(s.logits[j * NH + h] - m);
        s.mx[tid]  = m;
        s.den[tid] = (d == 0.f) ? 1.f : d;
    } else {
        const float4 z = make_float4(0.f, 0.f, 0.f, 0.f);
        for (int i = tid - 128; i < NV * AMS; i += 128) Amat4[i] = z;
    }
    __syncthreads();

    // --- per-edge alpha, scattered into dense Amat[dst][src] (float4 = 4 heads) ---
    {
        const int e = tid;
        const int dd = s.edst[e], ss = s.esrc[e];
        const float4 lg  = *reinterpret_cast<const float4*>(&s.logits[e * NH]);
        const float4 mxv = *reinterpret_cast<const float4*>(&s.mx[dd * NH]);
        const float4 dnv = *reinterpret_cast<const float4*>(&s.den[dd * NH]);
        float* am = Amat + (dd * AMS + ss) * 4;
        atomicAdd(am + 0, __expf(lg.x - mxv.x) / dnv.x);
        atomicAdd(am + 1, __expf(lg.y - mxv.y) / dnv.y);
        atomicAdd(am + 2, __expf(lg.z - mxv.z) / dnv.z);
        atomicAdd(am + 3, __expf(lg.w - mxv.w) / dnv.w);
    }
    __syncthreads();

    // --- dense aggregation: bufB[v] = sum_u Amat[v][u] (per head) * hs[u] ---
    {
        const int v = tid >> 3;        // 32 nodes
        const int l = tid & 7;         // 8 channel lanes
        float4 acc[8];
#pragma unroll
        for (int blk = 0; blk < 8; blk++) acc[blk] = make_float4(0.f, 0.f, 0.f, 0.f);
        const float4* AmV = Amat4 + v * AMS;
        for (int u = 0; u < NV; u++) {
            const float4 a4 = AmV[u];  // alphas for heads 0..3, broadcast across v-lanes
            const bool nz = (a4.x != 0.f) | (a4.y != 0.f) | (a4.z != 0.f) | (a4.w != 0.f);
            if (!__any_sync(0xffffffffu, nz)) continue;
            const float4* p = bufA4 + u * SR4;
#pragma unroll
            for (int blk = 0; blk < 8; blk++) {
                const int h = blk >> 1;
                const float a = (h == 0) ? a4.x : (h == 1) ? a4.y : (h == 2) ? a4.z : a4.w;
                fma4(acc[blk], a, p[blk * 8 + l]);
            }
        }
#pragma unroll
        for (int blk = 0; blk < 8; blk++) bufB4[v * SR4 + blk * 8 + l] = acc[blk];
    }
    __syncthreads();

    // --- head maxpool -> hT[k][v] and hN[v][k] ---
    float4* hN4 = reinterpret_cast<float4*>(s.hN);
    for (int i = tid; i < NV * DH / 4; i += NT) {
        const int v = i >> 4, q = i & 15;
        float4 m = bufB4[v * SR4 + q];
#pragma unroll
        for (int h = 1; h < NH; h++) {
            const float4 t = bufB4[v * SR4 + h * 16 + q];
            m.x = fmaxf(m.x, t.x); m.y = fmaxf(m.y, t.y);
            m.z = fmaxf(m.z, t.z); m.w = fmaxf(m.w, t.w);
        }
        hN4[v * HNS4 + q] = m;
        const int k0 = q * 4;
        s.hT[(k0 + 0) * STK + v] = m.x;
        s.hT[(k0 + 1) * STK + v] = m.y;
        s.hT[(k0 + 2) * STK + v] = m.z;
        s.hT[(k0 + 3) * STK + v] = m.w;
    }
    __syncthreads();
}

__global__ __launch_bounds__(NT, 2)
void gat_fused_kernel(const float* __restrict__ x,
                      const int* __restrict__ src,
                      const int* __restrict__ dst,
                      const float* __restrict__ W1s, const float* __restrict__ b1s,
                      const float* __restrict__ W1d, const float* __restrict__ b1d,
                      const float* __restrict__ a1,
                      const float* __restrict__ W2s, const float* __restrict__ b2s,
                      const float* __restrict__ W2d, const float* __restrict__ b2d,
                      const float* __restrict__ a2,
                      const float* __restrict__ Wg, const float* __restrict__ bg,
                      float* __restrict__ out)
{
    extern __shared__ unsigned char smraw[];
    Smem& s = *reinterpret_cast<Smem*>(smraw);
    const int g = blockIdx.x, tid = threadIdx.x;

    // ---- phase 0: load x transposed, count-sort edges by dst ----
    {
        const float* xg = x + (size_t)g * NV * K1;
        for (int i = tid; i < NV * K1; i += NT) {
            const int row = i >> 7, k = i & 127;
            s.xsT[k * STK + row] = __ldg(&xg[i]);
        }
        const int rs = src[g * NE + tid] - g * NV;
        const int rd = dst[g * NE + tid] - g * NV;
        if (tid < NV) s.cnt[tid] = 0;
        __syncthreads();
        const int p = atomicAdd(&s.cnt[rd], 1);
        __syncthreads();
        if (tid == 0) {
            int acc = 0;
            for (int v = 0; v < NV; v++) { s.startv[v] = acc; acc += s.cnt[v]; }
            s.startv[NV] = acc;
        }
        __syncthreads();
        const int j = s.startv[rd] + p;
        s.esrc[j] = rs;
        s.edst[j] = rd;
    }
    __syncthreads();

    float4* xsT4  = reinterpret_cast<float4*>(s.xsT);
    float4* hT4   = reinterpret_cast<float4*>(s.hT);
    float4* bufA4 = reinterpret_cast<float4*>(s.bufA);
    float4* bufB4 = reinterpret_cast<float4*>(s.bufB);

    // ---- layer 1 ----
    gemm<K1>(W1s, b1s, xsT4, bufA4, tid);
    gemm<K1>(W1d, b1d, xsT4, bufB4, tid);
    __syncthreads();
    gat_edge_phase(s, a1, tid);    // NOTE: destroys xsT (Amat alias)

    // ---- layer 2 ----
    gemm<K2>(W2s, b2s, hT4, bufA4, tid);
    gemm<K2>(W2d, b2d, hT4, bufB4, tid);
    __syncthreads();
    gat_edge_phase(s, a2, tid);    // overwrites hT/hN with h2

    // ---- global attention pooling ----
    if (tid < NV) {
        const float4* hN4 = reinterpret_cast<const float4*>(s.hN);
        const float4* wg4 = reinterpret_cast<const float4*>(Wg);
        float gacc = __ldg(&bg[0]);
#pragma unroll
        for (int q = 0; q < 16; q++) {
            const float4 hv = hN4[tid * HNS4 + q];
            const float4 w  = __ldg(&wg4[q]);
            gacc = fmaf(hv.x, w.x, gacc);
            gacc = fmaf(hv.y, w.y, gacc);
            gacc = fmaf(hv.z, w.z, gacc);
            gacc = fmaf(hv.w, w.w, gacc);
        }
        float m = gacc;
#pragma unroll
        for (int o = 16; o; o >>= 1) m = fmaxf(m, __shfl_xor_sync(0xffffffffu, m, o));
        const float ex = __expf(gacc - m);
        float d = ex;
#pragma unroll
        for (int o = 16; o; o >>= 1) d += __shfl_xor_sync(0xffffffffu, d, o);
        s.nalpha[tid] = ex / d;
    }
    __syncthreads();
    if (tid < DH) {
        float r = 0.f;
#pragma unroll
        for (int v = 0; v < NV; v++) r = fmaf(s.nalpha[v], s.hT[tid * STK + v], r);
        out[(size_t)g * DH + tid] = r;
    }
}

extern "C" void kernel_launch(void* const* d_in, const int* in_sizes, int n_in,
                              void* d_out, int out_size)
{
    const float* x   = (const float*)d_in[0];
    const int*   src = (const int*)d_in[1];
    const int*   dst = (const int*)d_in[2];
    const float* W1s = (const float*)d_in[4];
    const float* b1s = (const float*)d_in[5];
    const float* W1d = (const float*)d_in[6];
    const float* b1d = (const float*)d_in[7];
    const float* a1  = (const float*)d_in[8];
    const float* W2s = (const float*)d_in[9];
    const float* b2s = (const float*)d_in[10];
    const float* W2d = (const float*)d_in[11];
    const float* b2d = (const float*)d_in[12];
    const float* a2  = (const float*)d_in[13];
    const float* Wg  = (const float*)d_in[14];
    const float* bg  = (const float*)d_in[15];
    float* out = (float*)d_out;

    const int smem = (int)sizeof(Smem);
    cudaFuncSetAttribute(gat_fused_kernel,
                         cudaFuncAttributeMaxDynamicSharedMemorySize, smem);
    gat_fused_kernel<<<NGRAPHS, NT, smem>>>(x, src, dst,
                                            W1s, b1s, W1d, b1d, a1,
                                            W2s, b2s, W2d, b2d, a2,
                                            Wg, bg, out);
}